// round 4
// baseline (speedup 1.0000x reference)
#include <cuda_runtime.h>
#include <cuda_bf16.h>

// Shapes: A=1, B=8, M=256, H(=Kdim)=2048, E=8, K=2, N=2048
// out (scalar) = sum_{b,e,k} sp[b,e] * hsum[b,k] * wsum[e,k]
//   hsum[b,k] = sum_m hidden[0,b,m,k]
//   wsum[e,k] = sum_n W[0,e,k,n]

#define Bd 8
#define Md 256
#define Hd 2048
#define Ed 8
#define Nd 2048

__device__ float  g_hsum[Bd * Hd];   // 64 KB scratch
__device__ double g_acc;

// ---------------- kernel 0: zero scratch ----------------
__global__ void k_zero() {
    int i = blockIdx.x * blockDim.x + threadIdx.x;
    for (; i < Bd * Hd; i += gridDim.x * blockDim.x) g_hsum[i] = 0.0f;
    if (blockIdx.x == 0 && threadIdx.x == 0) g_acc = 0.0;
}

// ---------------- kernel 1: hsum[b,k] = sum_m hidden[b,m,k] ----------------
// grid: (Hd/4/256 = 2, Bd = 8, Md/16 = 16)  block: 256
__global__ void k_hsum(const float* __restrict__ hidden) {
    int k4 = blockIdx.x * blockDim.x + threadIdx.x;   // float4 index over k (0..511)
    int b  = blockIdx.y;
    int m0 = blockIdx.z * 16;

    const float4* src = reinterpret_cast<const float4*>(
        hidden + (size_t)(b * Md + m0) * Hd) + k4;

    float4 acc = make_float4(0.f, 0.f, 0.f, 0.f);
#pragma unroll
    for (int i = 0; i < 16; i++) {
        float4 v = src[i * (Hd / 4)];
        acc.x += v.x; acc.y += v.y; acc.z += v.z; acc.w += v.w;
    }
    float* dst = &g_hsum[b * Hd + k4 * 4];
    atomicAdd(dst + 0, acc.x);
    atomicAdd(dst + 1, acc.y);
    atomicAdd(dst + 2, acc.z);
    atomicAdd(dst + 3, acc.w);
}

// ---------------- kernel 2: main reduction over W (134 MB) ----------------
// One warp per (e,k) row of 2048 floats. grid: 16384/8 = 2048 blocks x 256.
__global__ void k_main(const float* __restrict__ W, const float* __restrict__ sp) {
    int warp = threadIdx.x >> 5;
    int lane = threadIdx.x & 31;
    int row  = blockIdx.x * 8 + warp;          // 0..16383 == e*2048 + k
    int e = row >> 11;
    int k = row & 2047;

    const float4* src = reinterpret_cast<const float4*>(W + (size_t)row * Nd);

    float s = 0.f;
#pragma unroll
    for (int i = 0; i < 16; i++) {             // 16 float4 per lane * 32 lanes = 2048 floats
        float4 v = src[lane + 32 * i];
        s += (v.x + v.y) + (v.z + v.w);
    }
#pragma unroll
    for (int off = 16; off > 0; off >>= 1)
        s += __shfl_xor_sync(0xffffffff, s, off);

    if (lane == 0) {
        // c[e,k] = sum_b sp[b,e] * hsum[b,k]   (sparsity layout: sp[b*K*E + 0*E + e])
        float c = 0.f;
#pragma unroll
        for (int b = 0; b < Bd; b++)
            c += sp[b * 16 + e] * g_hsum[b * Hd + k];
        atomicAdd(&g_acc, (double)s * (double)c);
    }
}

// ---------------- kernel 3: write output ----------------
__global__ void k_final(float* out) { out[0] = (float)g_acc; }

extern "C" void kernel_launch(void* const* d_in, const int* in_sizes, int n_in,
                              void* d_out, int out_size) {
    const float* hidden = (const float*)d_in[0];   // (1,8,256,2048)
    const float* sp     = (const float*)d_in[1];   // (1,8,2,8)
    const float* W      = (const float*)d_in[2];   // (1,8,2048,2048)
    float* out = (float*)d_out;

    k_zero<<<16, 256>>>();
    {
        dim3 grid(Hd / 4 / 256, Bd, Md / 16);
        k_hsum<<<grid, 256>>>(hidden);
    }
    k_main<<<(Ed * Hd) / 8, 256>>>(W, sp);
    k_final<<<1, 1>>>(out);
}

// round 8
// speedup vs baseline: 1.2800x; 1.2800x over previous
#include <cuda_runtime.h>
#include <cuda_bf16.h>

// Shapes: A=1, B=8, M=256, H(=Kdim)=2048, E=8, K=2, N=2048
// out (scalar) = sum_{b,e,k} sp[b,e] * hsum[b,k] * wsum[e,k]
//   hsum[b,k] = sum_m hidden[0,b,m,k]     (16 MB stream)
//   wsum[e,k] = sum_n W[0,e,k,n]          (134 MB stream)
// The two streams are independent -> fuse into ONE full-chip kernel.

#define Bd 8
#define Md 256
#define Hd 2048
#define Ed 8
#define Nd 2048

#define W_BLOCKS   2048            // 8 warps/block, 1 warp per (e,k) row
#define H_BLOCKS   256             // 16 m-chunks x 16 k-blocks
#define MCHUNKS    16

__device__ float  g_wsum[Ed * Hd];            // 64 KB
__device__ float  g_part[MCHUNKS * Bd * Hd];  // 1 MB partial hidden sums
__device__ double g_acc;
__device__ unsigned int g_done;

// ---------------- kernel 1: all 150 MB of streaming, one wave-set ----------------
__global__ void __launch_bounds__(256) k_stream(const float* __restrict__ W,
                                                const float* __restrict__ hidden) {
    if (blockIdx.x == 0 && threadIdx.x == 0) { g_acc = 0.0; g_done = 0u; }

    if (blockIdx.x < W_BLOCKS) {
        // ---- W row sums: one warp per row of 2048 floats ----
        int warp = threadIdx.x >> 5;
        int lane = threadIdx.x & 31;
        int row  = blockIdx.x * 8 + warp;            // e*2048 + k

        const float4* src = reinterpret_cast<const float4*>(W + (size_t)row * Nd);
        float s = 0.f;
#pragma unroll
        for (int i = 0; i < 16; i++) {               // 16 f4 * 32 lanes = 2048 floats
            float4 v = src[lane + 32 * i];
            s += (v.x + v.y) + (v.z + v.w);
        }
#pragma unroll
        for (int off = 16; off > 0; off >>= 1)
            s += __shfl_xor_sync(0xffffffff, s, off);
        if (lane == 0) g_wsum[row] = s;
    } else {
        // ---- hidden partial column sums: 64 KB per block, no atomics ----
        int idx = blockIdx.x - W_BLOCKS;             // 0..255
        int mc  = idx >> 4;                          // m chunk (0..15)
        int kb  = idx & 15;                          // k4 block (0..15)
        int g   = kb * 256 + threadIdx.x;            // 0..4095 = b*512 + k4
        int b   = g >> 9;
        int k4  = g & 511;
        int m0  = mc * 16;

        const float4* src = reinterpret_cast<const float4*>(
            hidden + (size_t)(b * Md + m0) * Hd) + k4;

        float4 acc = make_float4(0.f, 0.f, 0.f, 0.f);
#pragma unroll
        for (int i = 0; i < 16; i++) {
            float4 v = src[i * (Hd / 4)];
            acc.x += v.x; acc.y += v.y; acc.z += v.z; acc.w += v.w;
        }
        reinterpret_cast<float4*>(g_part)[mc * 4096 + g] = acc;
    }
}

// ---------------- kernel 2: tiny contraction + output (last-block-done) ----------------
__global__ void __launch_bounds__(256) k_combine(const float* __restrict__ sp,
                                                 float* __restrict__ out) {
    __shared__ float s_sp[Bd * Ed];
    __shared__ double s_red[256];

    if (threadIdx.x < Bd * Ed) {
        int b = threadIdx.x >> 3, e = threadIdx.x & 7;
        s_sp[threadIdx.x] = sp[b * 16 + e];          // sp layout (b, K=2, e): k-slice 0
    }
    __syncthreads();

    int k = blockIdx.x * 256 + threadIdx.x;          // 0..2047

    // hsum[b] = sum over 16 m-chunk partials
    float hs[Bd];
#pragma unroll
    for (int b = 0; b < Bd; b++) hs[b] = 0.f;
#pragma unroll
    for (int c = 0; c < MCHUNKS; c++) {
        const float* p = &g_part[c * Bd * Hd + k];
#pragma unroll
        for (int b = 0; b < Bd; b++) hs[b] += p[b * Hd];
    }

    double acc = 0.0;
#pragma unroll
    for (int e = 0; e < Ed; e++) {
        float c = 0.f;
#pragma unroll
        for (int b = 0; b < Bd; b++) c += s_sp[b * Ed + e] * hs[b];
        acc += (double)g_wsum[e * Hd + k] * (double)c;
    }

    // block reduce (double)
    s_red[threadIdx.x] = acc;
    __syncthreads();
    for (int s = 128; s > 0; s >>= 1) {
        if (threadIdx.x < s) s_red[threadIdx.x] += s_red[threadIdx.x + s];
        __syncthreads();
    }

    if (threadIdx.x == 0) {
        atomicAdd(&g_acc, s_red[0]);
        __threadfence();
        unsigned int ticket = atomicAdd(&g_done, 1u);
        if (ticket == gridDim.x - 1) {               // I'm last: all adds visible
            __threadfence();
            out[0] = (float)g_acc;
        }
    }
}

extern "C" void kernel_launch(void* const* d_in, const int* in_sizes, int n_in,
                              void* d_out, int out_size) {
    const float* hidden = (const float*)d_in[0];   // (1,8,256,2048)
    const float* sp     = (const float*)d_in[1];   // (1,8,2,8)
    const float* W      = (const float*)d_in[2];   // (1,8,2048,2048)
    float* out = (float*)d_out;

    k_stream<<<W_BLOCKS + H_BLOCKS, 256>>>(W, hidden);
    k_combine<<<Hd / 256, 256>>>(sp, out);
}

// round 9
// speedup vs baseline: 1.5269x; 1.1929x over previous
#include <cuda_runtime.h>
#include <cuda_bf16.h>

// Shapes: A=1, B=8, M=256, H(=Kdim)=2048, E=8, K=2, N=2048
// out (scalar) = sum_{b,e,k} sp[b,e] * hsum[b,k] * wsum[e,k]
//   hsum[b,k] = sum_m hidden[0,b,m,k]     (16 MB stream)
//   wsum[e,k] = sum_n W[0,e,k,n]          (134 MB stream)

#define Bd 8
#define Md 256
#define Hd 2048
#define Ed 8
#define Nd 2048

#define W_BLOCKS   2048            // 8 warps/block, 1 warp per (e,k) row
#define H_BLOCKS   256             // 16 m-chunks x 16 k-blocks
#define MCHUNKS    16

__device__ float  g_wsum[Ed * Hd];            // 64 KB
__device__ float  g_part[MCHUNKS * Bd * Hd];  // 1 MB partial hidden sums
__device__ double g_acc;
__device__ unsigned int g_done;

// ---------------- kernel 1: all 150 MB of streaming, one wave-set ----------------
__global__ void __launch_bounds__(256) k_stream(const float* __restrict__ W,
                                                const float* __restrict__ hidden) {
    if (blockIdx.x == 0 && threadIdx.x == 0) { g_acc = 0.0; g_done = 0u; }

    if (blockIdx.x < W_BLOCKS) {
        // ---- W row sums: one warp per row of 2048 floats ----
        int warp = threadIdx.x >> 5;
        int lane = threadIdx.x & 31;
        int row  = blockIdx.x * 8 + warp;            // e*2048 + k

        const float4* src = reinterpret_cast<const float4*>(W + (size_t)row * Nd);
        float s = 0.f;
#pragma unroll
        for (int i = 0; i < 16; i++) {               // 16 f4 * 32 lanes = 2048 floats
            float4 v = src[lane + 32 * i];
            s += (v.x + v.y) + (v.z + v.w);
        }
#pragma unroll
        for (int off = 16; off > 0; off >>= 1)
            s += __shfl_xor_sync(0xffffffff, s, off);
        if (lane == 0) g_wsum[row] = s;
    } else {
        // ---- hidden partial column sums: 64 KB per block, no atomics ----
        int idx = blockIdx.x - W_BLOCKS;             // 0..255
        int mc  = idx >> 4;                          // m chunk (0..15)
        int kb  = idx & 15;                          // k4 block (0..15)
        int g   = kb * 256 + threadIdx.x;            // 0..4095 = b*512 + k4
        int b   = g >> 9;
        int k4  = g & 511;
        int m0  = mc * 16;

        const float4* src = reinterpret_cast<const float4*>(
            hidden + (size_t)(b * Md + m0) * Hd) + k4;

        float4 acc = make_float4(0.f, 0.f, 0.f, 0.f);
#pragma unroll
        for (int i = 0; i < 16; i++) {
            float4 v = src[i * (Hd / 4)];
            acc.x += v.x; acc.y += v.y; acc.z += v.z; acc.w += v.w;
        }
        reinterpret_cast<float4*>(g_part)[mc * 4096 + g] = acc;   // [c][b][k] layout
    }
}

// ---------------- kernel 2: parallel contraction + output ----------------
// 64 blocks x 256 = 16384 threads; thread t owns (b = t>>11, k = t&2047).
// All loads coalesced (lanes = consecutive k), MLP=16 on g_part.
__global__ void __launch_bounds__(256) k_combine(const float* __restrict__ sp,
                                                 float* __restrict__ out) {
    int t = blockIdx.x * 256 + threadIdx.x;          // 0..16383
    int b = t >> 11;                                 // 0..7
    int k = t & 2047;                                // 0..2047

    // hsum[b,k] = sum over 16 m-chunk partials (independent loads -> MLP=16)
    float hs = 0.f;
#pragma unroll
    for (int c = 0; c < MCHUNKS; c++)
        hs += g_part[c * (Bd * Hd) + b * Hd + k];

    // cb = sum_e sp[b,e] * wsum[e,k]   (sp layout (b, K=2, e): k-slice 0)
    float cb = 0.f;
#pragma unroll
    for (int e = 0; e < Ed; e++)
        cb += sp[b * 16 + e] * g_wsum[e * Hd + k];

    double acc = (double)hs * (double)cb;

    // warp reduce (double), one atomic per warp
#pragma unroll
    for (int off = 16; off > 0; off >>= 1)
        acc += __shfl_xor_sync(0xffffffff, acc, off);
    if ((threadIdx.x & 31) == 0) atomicAdd(&g_acc, acc);

    // last-block-done writes the scalar output
    __syncthreads();
    if (threadIdx.x == 0) {
        __threadfence();
        unsigned int ticket = atomicAdd(&g_done, 1u);
        if (ticket == gridDim.x - 1) {
            __threadfence();
            out[0] = (float)g_acc;
        }
    }
}

extern "C" void kernel_launch(void* const* d_in, const int* in_sizes, int n_in,
                              void* d_out, int out_size) {
    const float* hidden = (const float*)d_in[0];   // (1,8,256,2048)
    const float* sp     = (const float*)d_in[1];   // (1,8,2,8)
    const float* W      = (const float*)d_in[2];   // (1,8,2048,2048)
    float* out = (float*)d_out;

    k_stream<<<W_BLOCKS + H_BLOCKS, 256>>>(W, hidden);
    k_combine<<<64, 256>>>(sp, out);
}